// round 17
// baseline (speedup 1.0000x reference)
#include <cuda_runtime.h>
#include <cuda_fp16.h>
#include <cstdint>

// InstanceConv via warp-level mma.sync f16 GEMM (compute_103-safe).
// Round 16: ratio-0.75 LDSM (warp = 2y x 32px x 32oc shares W across rows),
// 2x128 full-width tiles, W streamed via 4-slot cp.async ring (32KB) so
// 2 CTAs/SM still fit; work stealing; bulk X staging; direct-STG epilogue.
// B=8, C=64, OC=64, H=W=128, K=3, pad=1.

#define BATCH 8
#define CH 64
#define OCN 64
#define HDIM 128
#define WDIM 128
#define NTILES 512                   // 2-row x 128-px tiles
#define GRID_MAIN 304
#define NTHREADS 256
#define OUT_MASK_OFF (BATCH * OCN * HDIM * WDIM)   // 8388608
#define HW (HDIM * WDIM)

// ---- smem layout (bytes, per CTA) ----
#define OFF_WR 0                         // W ring: 4 slots x 8192
#define X_SLOT 16640                     // 130 rows x 128B (rows 0,129 garbage)
#define OFF_X (OFF_WR + 4 * 8192)        // 32768: 4 slots
#define OFF_M (OFF_X + 4 * X_SLOT)       // 99328: mask [4][132] f32 = 2112
#define OFF_B (OFF_M + 2112)             // 101440: bias
#define OFF_CTRL (OFF_B + 256)           // 101696: [0]=next tile; +16 mbar
#define SMEM_TOTAL (OFF_CTRL + 32)       // 101728 (x2 CTAs = 203456 <= 227KB)

__device__ uint32_t g_xt[BATCH * HDIM * WDIM * 32];  // [b][y]: 128 x-rows x 128B, swizzled
__device__ uint4 g_wimg[9 * 8192 / 16];              // [tap] 64(c)x64(o) f16, swizzled
__device__ int g_ctr;

__device__ __forceinline__ uint32_t smem_u32(const void* p) {
    uint32_t a;
    asm("{ .reg .u64 t; cvta.to.shared.u64 t, %1; cvt.u32.u64 %0, t; }" : "=r"(a) : "l"(p));
    return a;
}
__device__ __forceinline__ void ldsm_x4(uint32_t addr, uint32_t* r) {
    asm volatile("ldmatrix.sync.aligned.m8n8.x4.shared.b16 {%0,%1,%2,%3}, [%4];"
                 : "=r"(r[0]), "=r"(r[1]), "=r"(r[2]), "=r"(r[3]) : "r"(addr));
}
__device__ __forceinline__ void ldsm_x4t(uint32_t addr, uint32_t* r) {
    asm volatile("ldmatrix.sync.aligned.m8n8.x4.trans.shared.b16 {%0,%1,%2,%3}, [%4];"
                 : "=r"(r[0]), "=r"(r[1]), "=r"(r[2]), "=r"(r[3]) : "r"(addr));
}
__device__ __forceinline__ void mma_f16(float* d, const uint32_t* a, uint32_t b0, uint32_t b1) {
    asm volatile("mma.sync.aligned.m16n8k16.row.col.f32.f16.f16.f32 "
                 "{%0,%1,%2,%3}, {%4,%5,%6,%7}, {%8,%9}, {%0,%1,%2,%3};"
                 : "+f"(d[0]), "+f"(d[1]), "+f"(d[2]), "+f"(d[3])
                 : "r"(a[0]), "r"(a[1]), "r"(a[2]), "r"(a[3]), "r"(b0), "r"(b1));
}
__device__ __forceinline__ void cpasync16(uint32_t d, const void* s) {
    asm volatile("cp.async.ca.shared.global [%0], [%1], 16;"
                 :: "r"(d), "l"(s) : "memory");
}
#define CP_COMMIT() asm volatile("cp.async.commit_group;" ::: "memory")
#define MBARRIER_INIT(a, n) \
    asm volatile("mbarrier.init.shared.b64 [%0], %1;" :: "r"(a), "r"((uint32_t)(n)) : "memory")
#define MBARRIER_EXPECT_TX(a, tx) \
    asm volatile("mbarrier.arrive.expect_tx.shared.b64 _, [%0], %1;" \
                 :: "r"(a), "r"((uint32_t)(tx)) : "memory")
#define MBARRIER_WAIT_PARITY(a, par) do {                                         \
    uint32_t _m = (a); uint32_t _p = (uint32_t)(par); uint32_t _d;                \
    asm volatile("{\n\t.reg .pred p;\n\t"                                         \
        "mbarrier.try_wait.parity.acquire.cta.shared::cta.b64 p, [%1], %2;\n\t"   \
        "selp.b32 %0, 1, 0, p;\n\t}" : "=r"(_d) : "r"(_m), "r"(_p) : "memory");   \
    if (!_d) {                                                                    \
        asm volatile("{\n\t.reg .pred P1;\n\t"                                    \
            "WL_%=:\n\t"                                                          \
            "mbarrier.try_wait.parity.acquire.cta.shared::cta.b64 P1, [%0], %1, 0x989680;\n\t" \
            "@P1 bra.uni WD_%=;\n\tbra.uni WL_%=;\n\tWD_%=:\n\t}"                 \
            :: "r"(_m), "r"(_p) : "memory");                                      \
    }                                                                             \
} while (0)
#define FENCE_ASYNC() asm volatile("fence.proxy.async.shared::cta;" ::: "memory")
__device__ __forceinline__ void bulk_cp(uint32_t dst, const void* src, uint32_t bytes,
                                        uint32_t mbar) {
    asm volatile("cp.async.bulk.shared::cta.global.mbarrier::complete_tx::bytes "
                 "[%0], [%1], %2, [%3];"
                 :: "r"(dst), "l"(src), "r"(bytes), "r"(mbar) : "memory");
}

// ---------------- prep kernel ----------------
__global__ void prep(const float* __restrict__ inp, const float* __restrict__ conv) {
    const int tid = threadIdx.x;
    if (blockIdx.x >= 2048) {
        if (blockIdx.x == 2048 && tid == 0) g_ctr = GRID_MAIN;
        int i = (blockIdx.x - 2048) * 256 + tid;
        if (i < 9 * 64 * 64) {
            int o = i & 63, c = (i >> 6) & 63, tap = i >> 12;
            __half h = __float2half(conv[(o * 64 + c) * 9 + tap]);
            unsigned short* img = (unsigned short*)g_wimg;
            uint32_t byte = (uint32_t)(c * 128 + ((((o >> 3) ^ (c & 7))) << 4) + (o & 7) * 2);
            img[(tap * 8192 + byte) >> 1] = __half_as_ushort(h);
        }
        return;
    }
    __shared__ float tile[64][65];
    const int blk = blockIdx.x;
    const int half = blk & 1, y = (blk >> 1) & 127, b = blk >> 8;
    const int x0 = half * 64;
    #pragma unroll
    for (int i = 0; i < 16; ++i) {
        int idx = i * 256 + tid;
        int c = idx >> 6, x = idx & 63;
        tile[c][x] = inp[((b * CH + c) * HDIM + y) * WDIM + x0 + x];
    }
    __syncthreads();
    #pragma unroll
    for (int i = 0; i < 4; ++i) {
        int idx = i * 256 + tid;
        int x = (idx >> 4) + x0;
        int cw = (idx & 15) * 2;
        __half h0 = __float2half(tile[2 * cw][idx >> 4]);
        __half h1 = __float2half(tile[2 * cw + 1][idx >> 4]);
        __half h2 = __float2half(tile[2 * cw + 2][idx >> 4]);
        __half h3 = __float2half(tile[2 * cw + 3][idx >> 4]);
        uint2 v;
        v.x = (uint32_t)__half_as_ushort(h0) | ((uint32_t)__half_as_ushort(h1) << 16);
        v.y = (uint32_t)__half_as_ushort(h2) | ((uint32_t)__half_as_ushort(h3) << 16);
        int u = cw >> 2;
        int dst = ((b * HDIM + y) << 12) + (x << 5)
                + (((u ^ (x & 7))) << 2) + (cw & 3);
        *reinterpret_cast<uint2*>(g_xt + dst) = v;
    }
}

// ---------------- main persistent kernel ----------------
__global__ __launch_bounds__(NTHREADS, 2)
void instconv_mma(const float* __restrict__ mask,
                  const float* __restrict__ bias,
                  float* __restrict__ out) {
    extern __shared__ char smem[];
    const uint32_t sb = smem_u32(smem);
    const int tid = threadIdx.x;
    const int wid = tid >> 5;
    const int lane = tid & 31;
    const int g = lane >> 2;
    const int t2 = (lane & 3) * 2;
    const int och = wid >> 2;         // oc half
    const int p0 = (wid & 3) * 32;    // 32-px group within 128-px tile
    const int lane15 = lane & 15;
    const int laneHi = lane >> 4;

    volatile int* sCtrl = (volatile int*)(smem + OFF_CTRL);
    const uint32_t mbar = sb + OFF_CTRL + 16;

    if (tid < 64) ((float*)(smem + OFF_B))[tid] = bias[tid];
    if (tid == 0) MBARRIER_INIT(mbar, 1);
    const float* sB = (const float*)(smem + OFF_B);
    float* sM = (float*)(smem + OFF_M);

    uint32_t wcs[2];
    #pragma unroll
    for (int j = 0; j < 2; ++j)
        wcs[j] = (uint32_t)(((((2 * och + j) * 2 + laneHi) ^ (lane & 7))) << 4);

    // W ring staging helper (content tap -> ring slot), one cp.async group
    #define STAGE_WTAP(content, slot) do {                                        \
        const char* _src = (const char*)g_wimg + (content) * 8192;                \
        uint32_t _dst = sb + OFF_WR + (uint32_t)((slot) * 8192);                  \
        cpasync16(_dst + tid * 16, _src + tid * 16);                              \
        cpasync16(_dst + (tid + 256) * 16, _src + (tid + 256) * 16);              \
        CP_COMMIT();                                                              \
    } while (0)

    int wbase = 0;

    // ---- prologue: stage first tile ----
    int t = blockIdx.x;
    {
        const int b = t >> 6, y0 = (t & 63) * 2;
        STAGE_WTAP(0, 0);
        STAGE_WTAP(1, 1);
        STAGE_WTAP(2, 2);
        if (tid == 0) {
            FENCE_ASYNC();
            MBARRIER_EXPECT_TX(mbar, 4 * 16384);
            #pragma unroll
            for (int s = 0; s < 4; ++s) {
                int ys = y0 - 1 + s; ys = ys < 0 ? 0 : (ys > 127 ? 127 : ys);
                bulk_cp(sb + OFF_X + s * X_SLOT + 128,
                        (const char*)g_xt + (((size_t)(b * HDIM + ys)) << 14),
                        16384, mbar);
            }
        }
        for (int i = tid; i < 4 * 132; i += NTHREADS) {
            int r = i / 132, xi = i - r * 132;
            int ys = y0 + r - 1, xs = xi - 1;
            float v = -1.0f;
            if ((unsigned)ys < (unsigned)HDIM && (unsigned)xs < (unsigned)WDIM && xi < 130)
                v = mask[(b * HDIM + ys) * WDIM + xs];
            sM[i] = v;
        }
        if (tid == 0) sCtrl[0] = atomicAdd(&g_ctr, 1);
    }
    __syncthreads();   // mask + sCtrl visible

    int ph = 0;

    for (;;) {
        const int b = t >> 6, y0 = (t & 63) * 2;

        MBARRIER_WAIT_PARITY(mbar, ph); ph ^= 1;
        const int tn = sCtrl[0];
        const bool have_next = tn < NTILES;
        __syncthreads();
        if (tid == 0) sCtrl[0] = atomicAdd(&g_ctr, 1);

        // centers per (y, pxfrag)
        float cA[2][2], cB[2][2];
        #pragma unroll
        for (int y = 0; y < 2; ++y)
            #pragma unroll
            for (int f = 0; f < 2; ++f) {
                cA[y][f] = sM[(y + 1) * 132 + 1 + p0 + f * 16 + g];
                cB[y][f] = sM[(y + 1) * 132 + 1 + p0 + f * 16 + g + 8];
            }

        float D[2][2][4][4];
        #pragma unroll
        for (int y = 0; y < 2; ++y)
            #pragma unroll
            for (int f = 0; f < 2; ++f)
                #pragma unroll
                for (int q = 0; q < 4; ++q)
                    #pragma unroll
                    for (int j = 0; j < 4; ++j) D[y][f][q][j] = 0.0f;

        #pragma unroll
        for (int ky = 0; ky < 3; ++ky) {
            #pragma unroll
            for (int kx = 0; kx < 3; ++kx) {
                const int tap = ky * 3 + kx;
                asm volatile("cp.async.wait_group 2;" ::: "memory");
                __syncthreads();   // W slot for this tap visible to all

                uint32_t mkA[2][2], mkB[2][2];
                #pragma unroll
                for (int y = 0; y < 2; ++y)
                    #pragma unroll
                    for (int f = 0; f < 2; ++f) {
                        const int idx = (y + ky) * 132 + p0 + f * 16 + g + kx;
                        mkA[y][f] = (sM[idx] == cA[y][f]) ? 0xFFFFFFFFu : 0u;
                        mkB[y][f] = (sM[idx + 8] == cB[y][f]) ? 0xFFFFFFFFu : 0u;
                    }

                const uint32_t wTap = sb + OFF_WR
                    + (uint32_t)(((wbase + tap) & 3) * 8192 + lane15 * 128);
                const uint32_t rowb = (uint32_t)((p0 + lane15 + kx) * 128);
                const int xorm = (lane15 + kx + 7) & 7;
                const uint32_t sA0 = sb + OFF_X + (uint32_t)(ky * X_SLOT) + rowb;
                const uint32_t sA1 = sA0 + X_SLOT;

                #pragma unroll
                for (int k = 0; k < 4; ++k) {
                    const uint32_t colA = (uint32_t)(((k * 2 + laneHi) ^ xorm) << 4);
                    uint32_t a[2][2][4];
                    ldsm_x4(sA0 + colA, a[0][0]);
                    ldsm_x4(sA0 + 2048 + colA, a[0][1]);
                    ldsm_x4(sA1 + colA, a[1][0]);
                    ldsm_x4(sA1 + 2048 + colA, a[1][1]);
                    #pragma unroll
                    for (int y = 0; y < 2; ++y)
                        #pragma unroll
                        for (int f = 0; f < 2; ++f) {
                            a[y][f][0] &= mkA[y][f]; a[y][f][2] &= mkA[y][f];
                            a[y][f][1] &= mkB[y][f]; a[y][f][3] &= mkB[y][f];
                        }

                    const uint32_t wk = wTap + (uint32_t)(k * 2048);
                    {
                        uint32_t w0[4];
                        ldsm_x4t(wk + wcs[0], w0);
                        #pragma unroll
                        for (int y = 0; y < 2; ++y)
                            #pragma unroll
                            for (int f = 0; f < 2; ++f) {
                                mma_f16(D[y][f][0], a[y][f], w0[0], w0[1]);
                                mma_f16(D[y][f][1], a[y][f], w0[2], w0[3]);
                            }
                    }
                    {
                        uint32_t w1[4];
                        ldsm_x4t(wk + wcs[1], w1);
                        #pragma unroll
                        for (int y = 0; y < 2; ++y)
                            #pragma unroll
                            for (int f = 0; f < 2; ++f) {
                                mma_f16(D[y][f][2], a[y][f], w1[0], w1[1]);
                                mma_f16(D[y][f][3], a[y][f], w1[2], w1[3]);
                            }
                    }
                }
                // refill ring: content (tap+3)%9 into slot (wbase+tap+3)&3
                STAGE_WTAP((tap + 3) % 9, (wbase + tap + 3) & 3);
            }
        }
        __syncthreads();   // all X/sM compute reads done

        // stage NEXT tile's X (overlaps epilogue + sibling CTA's compute)
        const int bn = tn >> 6, yn0 = (tn & 63) * 2;
        if (tid == 0 && have_next) {
            FENCE_ASYNC();
            MBARRIER_EXPECT_TX(mbar, 4 * 16384);
            #pragma unroll
            for (int s = 0; s < 4; ++s) {
                int ys = yn0 - 1 + s; ys = ys < 0 ? 0 : (ys > 127 ? 127 : ys);
                bulk_cp(sb + OFF_X + s * X_SLOT + 128,
                        (const char*)g_xt + (((size_t)(bn * HDIM + ys)) << 14),
                        16384, mbar);
            }
        }

        // prefetch next-tile mask into registers
        float mr[3] = {-1.0f, -1.0f, -1.0f};
        if (have_next) {
            #pragma unroll
            for (int j = 0; j < 3; ++j) {
                int i = tid + j * NTHREADS;
                if (i < 4 * 132) {
                    int r = i / 132, xi = i - r * 132;
                    int ys = yn0 + r - 1, xs = xi - 1;
                    if ((unsigned)ys < (unsigned)HDIM && (unsigned)xs < (unsigned)WDIM && xi < 130)
                        mr[j] = mask[(bn * HDIM + ys) * WDIM + xs];
                }
            }
        }

        // inv factors
        float invA[2][2], invB[2][2];
        #pragma unroll
        for (int y = 0; y < 2; ++y)
            #pragma unroll
            for (int f = 0; f < 2; ++f) {
                float nA = 0.0f, nB = 0.0f;
                #pragma unroll
                for (int ky2 = 0; ky2 < 3; ++ky2)
                    #pragma unroll
                    for (int kx2 = 0; kx2 < 3; ++kx2) {
                        const int idx = (y + ky2) * 132 + p0 + f * 16 + g + kx2;
                        nA += (sM[idx] == cA[y][f]) ? 1.0f : 0.0f;
                        nB += (sM[idx + 8] == cB[y][f]) ? 1.0f : 0.0f;
                    }
                invA[y][f] = 9.0f / nA;   // cnt >= 1
                invB[y][f] = 9.0f / nB;
            }

        // direct-STG epilogue
        #pragma unroll
        for (int y = 0; y < 2; ++y)
            #pragma unroll
            for (int f = 0; f < 2; ++f)
                #pragma unroll
                for (int q = 0; q < 4; ++q) {
                    const int o0 = och * 32 + q * 8 + t2;
                    const float b0v = sB[o0], b1v = sB[o0 + 1];
                    float* ra = out + (((size_t)b * OCN + o0) * HDIM + y0 + y) * WDIM
                              + p0 + f * 16;
                    float* rb = ra + (size_t)HW;   // o0+1
                    const float iA = invA[y][f], iB = invB[y][f];
                    ra[g]     = D[y][f][q][0] * iA + b0v;
                    rb[g]     = D[y][f][q][1] * iA + b1v;
                    ra[g + 8] = D[y][f][q][2] * iB + b0v;
                    rb[g + 8] = D[y][f][q][3] * iB + b1v;
                }
        // mask passthrough: 2 rows x 128 px
        {
            const int r = tid >> 7, px = tid & 127;
            out[OUT_MASK_OFF + (b * HDIM + y0 + r) * WDIM + px] =
                sM[(r + 1) * 132 + 1 + px];
        }
        __syncthreads();   // all sM reads done before overwrite

        #pragma unroll
        for (int j = 0; j < 3; ++j) {
            int i = tid + j * NTHREADS;
            if (i < 4 * 132) sM[i] = mr[j];
        }
        __syncthreads();

        wbase = (wbase + 1) & 3;   // 9 taps ≡ 1 (mod 4)
        if (!have_next) break;
        t = tn;
    }
    asm volatile("cp.async.wait_group 0;" ::: "memory");
    #undef STAGE_WTAP
}

extern "C" void kernel_launch(void* const* d_in, const int* in_sizes, int n_in,
                              void* d_out, int out_size) {
    const float* inp  = (const float*)d_in[0];
    const float* mask = (const float*)d_in[1];
    const float* conv = (const float*)d_in[2];
    const float* bias = (const float*)d_in[3];
    float* out = (float*)d_out;
    (void)in_sizes; (void)n_in; (void)out_size;

    cudaFuncSetAttribute(instconv_mma,
                         cudaFuncAttributeMaxDynamicSharedMemorySize, SMEM_TOTAL);

    prep<<<2048 + 144, 256>>>(inp, conv);
    instconv_mma<<<GRID_MAIN, NTHREADS, SMEM_TOTAL>>>(mask, bias, out);
}